// round 1
// baseline (speedup 1.0000x reference)
#include <cuda_runtime.h>
#include <math.h>

#define NB   1024
#define NC   119
#define ND   1024
#define NH   16
#define SEQ  64
#define MR   (NB*SEQ)     // 65536 rows
#define KPAD 128

// ---------------- scratch (static device allocations; no cudaMalloc) -------
__device__ float g_xin [(size_t)MR * KPAD];   // transposed board, K padded
__device__ float g_embW[(size_t)KPAD * ND];   // zero-padded embedding weight
__device__ float g_x   [(size_t)MR * ND];     // x after embed (+pos); reused as y
__device__ float g_q   [(size_t)MR * ND];
__device__ float g_k   [(size_t)MR * ND];
__device__ float g_v   [(size_t)MR * ND];
__device__ float g_o   [(size_t)MR * ND];

// ---------------- pad embedding weight (119 -> 128 rows) -------------------
__global__ void pad_embW_kernel(const float* __restrict__ embW) {
    int idx = blockIdx.x * blockDim.x + threadIdx.x;
    if (idx >= KPAD * ND) return;
    int k = idx / ND, n = idx - k * ND;
    g_embW[idx] = (k < NC) ? embW[(size_t)k * ND + n] : 0.f;
}

// ---------------- board (B,C,64) -> xin (B*64, KPAD), zero pad -------------
__global__ void board_transpose_kernel(const float* __restrict__ board) {
    __shared__ float tile[NC * 65];
    int b = blockIdx.x;
    const float* src = board + (size_t)b * NC * SEQ;
    for (int i = threadIdx.x; i < NC * SEQ; i += blockDim.x) {
        int c = i >> 6, s = i & 63;
        tile[c * 65 + s] = src[i];
    }
    __syncthreads();
    float* dst = g_xin + (size_t)b * SEQ * KPAD;
    for (int i = threadIdx.x; i < SEQ * KPAD; i += blockDim.x) {
        int s = i >> 7, c = i & 127;
        dst[i] = (c < NC) ? tile[c * 65 + s] : 0.f;
    }
}

// ---------------- fp32 SGEMM: C = A(MxK) * B(KxN) + bias (+res) (+pos) -----
// BM=BN=128, BK=8, 256 threads, 8x8 per thread
__global__ __launch_bounds__(256, 2)
void sgemm_kernel(const float* __restrict__ A, const float* __restrict__ B,
                  const float* __restrict__ bias,
                  const float* __restrict__ res,   // residual, same MxN layout (nullable)
                  const float* __restrict__ pos,   // positional (64 x N), indexed m&63 (nullable)
                  float* __restrict__ C, int N, int K)
{
    __shared__ float As[8][132];   // padded: conflict-free transposed stores
    __shared__ float Bs[8][128];

    const int tid = threadIdx.x;
    const int bm = blockIdx.y * 128;
    const int bn = blockIdx.x * 128;
    const int tx = tid & 15, ty = tid >> 4;

    const int arow = tid >> 1, acol = (tid & 1) * 4;
    const int brow = tid >> 5, bcol = (tid & 31) * 4;

    const float* Ap = A + (size_t)(bm + arow) * K + acol;
    const float* Bp = B + (size_t)brow * N + bn + bcol;

    float acc[8][8];
    #pragma unroll
    for (int i = 0; i < 8; i++)
        #pragma unroll
        for (int j = 0; j < 8; j++) acc[i][j] = 0.f;

    for (int k0 = 0; k0 < K; k0 += 8) {
        float4 a4 = *(const float4*)(Ap + k0);
        As[acol + 0][arow] = a4.x;
        As[acol + 1][arow] = a4.y;
        As[acol + 2][arow] = a4.z;
        As[acol + 3][arow] = a4.w;
        float4 b4 = *(const float4*)(Bp + (size_t)k0 * N);
        *(float4*)&Bs[brow][bcol] = b4;
        __syncthreads();
        #pragma unroll
        for (int kk = 0; kk < 8; kk++) {
            float4 a0 = *(const float4*)&As[kk][ty * 8];
            float4 a1 = *(const float4*)&As[kk][ty * 8 + 4];
            float4 b0 = *(const float4*)&Bs[kk][tx * 8];
            float4 b1 = *(const float4*)&Bs[kk][tx * 8 + 4];
            float ra[8] = {a0.x,a0.y,a0.z,a0.w,a1.x,a1.y,a1.z,a1.w};
            float rb[8] = {b0.x,b0.y,b0.z,b0.w,b1.x,b1.y,b1.z,b1.w};
            #pragma unroll
            for (int i = 0; i < 8; i++)
                #pragma unroll
                for (int j = 0; j < 8; j++)
                    acc[i][j] = fmaf(ra[i], rb[j], acc[i][j]);
        }
        __syncthreads();
    }

    #pragma unroll
    for (int i = 0; i < 8; i++) {
        int m = bm + ty * 8 + i;
        size_t row = (size_t)m * N;
        #pragma unroll
        for (int j = 0; j < 8; j += 4) {
            int n = bn + tx * 8 + j;
            float4 c4;
            float4 bb = *(const float4*)&bias[n];
            c4.x = acc[i][j+0] + bb.x;
            c4.y = acc[i][j+1] + bb.y;
            c4.z = acc[i][j+2] + bb.z;
            c4.w = acc[i][j+3] + bb.w;
            if (res) {
                float4 r4 = *(const float4*)&res[row + n];
                c4.x += r4.x; c4.y += r4.y; c4.z += r4.z; c4.w += r4.w;
            }
            if (pos) {
                float4 p4 = *(const float4*)&pos[(size_t)(m & 63) * N + n];
                c4.x += p4.x; c4.y += p4.y; c4.z += p4.z; c4.w += p4.w;
            }
            *(float4*)&C[row + n] = c4;
        }
    }
}

// ---------------- attention: one block per (b,h) ---------------------------
// scores = q k^T / 8 + rel_bias[h]; softmax rows; o = p v
__global__ __launch_bounds__(256)
void attn_kernel(const float* __restrict__ rel_bias)
{
    extern __shared__ float sm[];
    float* qst = sm;              // [64][68] transposed: qst[d][s]
    float* kst = sm + 64 * 68;    // [64][68]
    float* vs  = sm + 2 * 64 * 68;// [64][64]  vs[j][d]
    float* ps  = vs + 64 * 64;    // [64][64]  probabilities

    const int h = blockIdx.x, b = blockIdx.y;
    const int tid = threadIdx.x;
    const size_t base = (size_t)b * SEQ * ND + h * 64;

    for (int i = tid; i < 64 * 64; i += 256) {
        int s = i >> 6, d = i & 63;
        size_t g = base + (size_t)s * ND + d;
        qst[d * 68 + s] = g_q[g];
        kst[d * 68 + s] = g_k[g];
        vs [s * 64 + d] = g_v[g];
    }
    __syncthreads();

    const int tj = tid & 15, ti = tid >> 4;
    const int i0 = ti * 4, j0 = tj * 4;

    float acc[4][4];
    #pragma unroll
    for (int a = 0; a < 4; a++)
        #pragma unroll
        for (int c = 0; c < 4; c++) acc[a][c] = 0.f;

    #pragma unroll 4
    for (int d = 0; d < 64; d++) {
        float4 qv = *(const float4*)&qst[d * 68 + i0];
        float4 kv = *(const float4*)&kst[d * 68 + j0];
        float qa[4] = {qv.x, qv.y, qv.z, qv.w};
        float kb[4] = {kv.x, kv.y, kv.z, kv.w};
        #pragma unroll
        for (int a = 0; a < 4; a++)
            #pragma unroll
            for (int c = 0; c < 4; c++)
                acc[a][c] = fmaf(qa[a], kb[c], acc[a][c]);
    }

    const float* rb = rel_bias + (size_t)h * 64 * 64;
    #pragma unroll
    for (int a = 0; a < 4; a++) {
        float4 b4 = *(const float4*)&rb[(i0 + a) * 64 + j0];
        acc[a][0] = acc[a][0] * 0.125f + b4.x;
        acc[a][1] = acc[a][1] * 0.125f + b4.y;
        acc[a][2] = acc[a][2] * 0.125f + b4.z;
        acc[a][3] = acc[a][3] * 0.125f + b4.w;
    }

    // softmax across each row: 16 lanes (tj) hold the row; reduce via shfl_xor
    #pragma unroll
    for (int a = 0; a < 4; a++) {
        float mx = fmaxf(fmaxf(acc[a][0], acc[a][1]), fmaxf(acc[a][2], acc[a][3]));
        #pragma unroll
        for (int off = 1; off < 16; off <<= 1)
            mx = fmaxf(mx, __shfl_xor_sync(0xffffffffu, mx, off));
        float s = 0.f;
        #pragma unroll
        for (int c = 0; c < 4; c++) { acc[a][c] = __expf(acc[a][c] - mx); s += acc[a][c]; }
        #pragma unroll
        for (int off = 1; off < 16; off <<= 1)
            s += __shfl_xor_sync(0xffffffffu, s, off);
        float inv = 1.f / s;
        #pragma unroll
        for (int c = 0; c < 4; c++) acc[a][c] *= inv;
        *(float4*)&ps[(i0 + a) * 64 + j0] =
            make_float4(acc[a][0], acc[a][1], acc[a][2], acc[a][3]);
    }
    __syncthreads();

    // o[i][d] = sum_j p[i][j] * v[j][d];  thread tile rows i0..+3, cols j0..+3
    float oc[4][4];
    #pragma unroll
    for (int a = 0; a < 4; a++)
        #pragma unroll
        for (int c = 0; c < 4; c++) oc[a][c] = 0.f;

    #pragma unroll 4
    for (int j = 0; j < 64; j++) {
        float4 vv = *(const float4*)&vs[j * 64 + j0];
        float vb[4] = {vv.x, vv.y, vv.z, vv.w};
        float pa[4];
        #pragma unroll
        for (int a = 0; a < 4; a++) pa[a] = ps[(i0 + a) * 64 + j];
        #pragma unroll
        for (int a = 0; a < 4; a++)
            #pragma unroll
            for (int c = 0; c < 4; c++)
                oc[a][c] = fmaf(pa[a], vb[c], oc[a][c]);
    }

    #pragma unroll
    for (int a = 0; a < 4; a++)
        *(float4*)&g_o[base + (size_t)(i0 + a) * ND + j0] =
            make_float4(oc[a][0], oc[a][1], oc[a][2], oc[a][3]);
}

// ---------------- LayerNorm over D=1024; one block per row -----------------
__device__ __forceinline__ float block_sum(float v, float* red) {
    #pragma unroll
    for (int o = 16; o > 0; o >>= 1) v += __shfl_xor_sync(0xffffffffu, v, o);
    int w = threadIdx.x >> 5;
    if ((threadIdx.x & 31) == 0) red[w] = v;
    __syncthreads();
    if (threadIdx.x < 8) {
        v = red[threadIdx.x];
        #pragma unroll
        for (int o = 4; o > 0; o >>= 1) v += __shfl_xor_sync(0xffu, v, o);
        if (threadIdx.x == 0) red[0] = v;
    }
    __syncthreads();
    float r = red[0];
    __syncthreads();
    return r;
}

__global__ __launch_bounds__(256)
void ln_kernel(const float* __restrict__ gamma, const float* __restrict__ beta,
               float* __restrict__ out)
{
    __shared__ float red[32];
    const size_t row = (size_t)blockIdx.x * ND;
    const int t4 = threadIdx.x * 4;
    float4 v = *(const float4*)&g_x[row + t4];

    float s = v.x + v.y + v.z + v.w;
    float mu = block_sum(s, red) * (1.f / ND);

    float dx = v.x - mu, dy = v.y - mu, dz = v.z - mu, dw = v.w - mu;
    float sq = dx * dx + dy * dy + dz * dz + dw * dw;
    float var = block_sum(sq, red) * (1.f / ND);
    float inv = rsqrtf(var + 1e-5f);

    float4 g4 = *(const float4*)&gamma[t4];
    float4 b4 = *(const float4*)&beta[t4];
    float4 o4;
    o4.x = dx * inv * g4.x + b4.x;
    o4.y = dy * inv * g4.y + b4.y;
    o4.z = dz * inv * g4.z + b4.z;
    o4.w = dw * inv * g4.w + b4.w;
    *(float4*)&out[row + t4] = o4;
}

// ---------------- launch ----------------------------------------------------
extern "C" void kernel_launch(void* const* d_in, const int* in_sizes, int n_in,
                              void* d_out, int out_size)
{
    const float* board = (const float*)d_in[0];
    const float* embW  = (const float*)d_in[1];
    const float* embB  = (const float*)d_in[2];
    const float* pos   = (const float*)d_in[3];
    const float* Wq    = (const float*)d_in[4];
    const float* bq    = (const float*)d_in[5];
    const float* Wk    = (const float*)d_in[6];
    const float* bk    = (const float*)d_in[7];
    const float* Wv    = (const float*)d_in[8];
    const float* bv    = (const float*)d_in[9];
    const float* Wo    = (const float*)d_in[10];
    const float* bo    = (const float*)d_in[11];
    const float* relb  = (const float*)d_in[12];
    const float* lng   = (const float*)d_in[13];
    const float* lnb   = (const float*)d_in[14];
    float* out = (float*)d_out;

    float *xin, *embWp, *x, *q, *k, *v, *o;
    cudaGetSymbolAddress((void**)&xin,   g_xin);
    cudaGetSymbolAddress((void**)&embWp, g_embW);
    cudaGetSymbolAddress((void**)&x,     g_x);
    cudaGetSymbolAddress((void**)&q,     g_q);
    cudaGetSymbolAddress((void**)&k,     g_k);
    cudaGetSymbolAddress((void**)&v,     g_v);
    cudaGetSymbolAddress((void**)&o,     g_o);

    pad_embW_kernel<<<(KPAD * ND + 255) / 256, 256>>>(embW);
    board_transpose_kernel<<<NB, 256>>>(board);

    dim3 gemm_grid(ND / 128, MR / 128);
    // x = xin @ embW + emb_b + positional
    sgemm_kernel<<<gemm_grid, 256>>>(xin, embWp, embB, nullptr, pos, x, ND, KPAD);
    // q, k, v
    sgemm_kernel<<<gemm_grid, 256>>>(x, Wq, bq, nullptr, nullptr, q, ND, ND);
    sgemm_kernel<<<gemm_grid, 256>>>(x, Wk, bk, nullptr, nullptr, k, ND, ND);
    sgemm_kernel<<<gemm_grid, 256>>>(x, Wv, bv, nullptr, nullptr, v, ND, ND);

    // attention
    const int attn_smem = (2 * 64 * 68 + 2 * 64 * 64) * (int)sizeof(float); // 67584
    cudaFuncSetAttribute(attn_kernel, cudaFuncAttributeMaxDynamicSharedMemorySize, attn_smem);
    attn_kernel<<<dim3(NH, NB), 256, attn_smem>>>(relb);

    // y = x + o @ Wo + bo   (written back into g_x)
    sgemm_kernel<<<gemm_grid, 256>>>(o, Wo, bo, x, nullptr, x, ND, ND);

    // out = LayerNorm(y)
    ln_kernel<<<MR, 256>>>(lng, lnb, out);
}

// round 3
// speedup vs baseline: 2.4366x; 2.4366x over previous
#include <cuda_runtime.h>
#include <cstdint>
#include <math.h>

#define NB   1024
#define NC   119
#define ND   1024
#define NH   16
#define SEQ  64
#define MR   (NB*SEQ)     // 65536 rows
#define KPAD 128
#define PADK 20           // smem row pitch in floats (16 + 4 pad)

// ---------------- scratch ----------------------------------------------------
__device__ float g_xin [(size_t)MR * KPAD];
__device__ float g_Wt  [(size_t)ND * ND];     // transposed weight (reused sequentially)
__device__ float g_x   [(size_t)MR * ND];
__device__ float g_q   [(size_t)MR * ND];
__device__ float g_k   [(size_t)MR * ND];
__device__ float g_v   [(size_t)MR * ND];
__device__ float g_o   [(size_t)MR * ND];

// ---------------- helpers -----------------------------------------------------
__device__ __forceinline__ uint32_t f2tf32(float f) {
    uint32_t r; asm("cvt.rna.tf32.f32 %0, %1;" : "=r"(r) : "f"(f)); return r;
}

__device__ __forceinline__ void mma_tf32(float* d, const uint32_t* a, const uint32_t* b) {
    asm volatile("mma.sync.aligned.m16n8k8.row.col.f32.tf32.tf32.f32 "
        "{%0,%1,%2,%3}, {%4,%5,%6,%7}, {%8,%9}, {%0,%1,%2,%3};"
        : "+f"(d[0]), "+f"(d[1]), "+f"(d[2]), "+f"(d[3])
        : "r"(a[0]), "r"(a[1]), "r"(a[2]), "r"(a[3]), "r"(b[0]), "r"(b[1]));
}

// ---------------- board (B,C,8,8) -> xin (B*64, KPAD) ------------------------
__global__ void board_transpose_kernel(const float* __restrict__ board) {
    __shared__ float tile[NC * 65];
    int b = blockIdx.x;
    const float* src = board + (size_t)b * NC * SEQ;
    for (int i = threadIdx.x; i < NC * SEQ; i += blockDim.x) {
        int c = i >> 6, s = i & 63;
        tile[c * 65 + s] = src[i];
    }
    __syncthreads();
    float* dst = g_xin + (size_t)b * SEQ * KPAD;
    for (int i = threadIdx.x; i < SEQ * KPAD; i += blockDim.x) {
        int s = i >> 7, c = i & 127;
        dst[i] = (c < NC) ? tile[c * 65 + s] : 0.f;
    }
}

// ---------------- weight transpose W(R x Cw) -> Wt(Cw x Rpad), zero pad ------
__global__ void transpose_kernel(const float* __restrict__ W, float* __restrict__ Wt,
                                 int R, int Cw, int Rpad) {
    __shared__ float t[32][33];
    int bx = blockIdx.x * 32;  // col of W
    int by = blockIdx.y * 32;  // row of W (padded range)
    int tx = threadIdx.x, ty = threadIdx.y;
    #pragma unroll
    for (int i = 0; i < 4; i++) {
        int r = by + ty + i * 8, c = bx + tx;
        t[ty + i * 8][tx] = (r < R) ? W[(size_t)r * Cw + c] : 0.f;
    }
    __syncthreads();
    #pragma unroll
    for (int i = 0; i < 4; i++) {
        int c = bx + ty + i * 8, r = by + tx;  // Wt[c][r]
        Wt[(size_t)c * Rpad + r] = t[tx][ty + i * 8];
    }
}

// ---------------- tf32 mma.sync GEMM -------------------------------------------
// C(M x ND) = A(M x K) @ Bt(ND x K)^T + bias (+res) (+pos)
// CTA 128x128, BK=16. 8 warps as 2(m) x 4(n); warp tile 64x32 via m16n8k8.
__global__ __launch_bounds__(256, 2)
void gemm_mma_kernel(const float* __restrict__ A, const float* __restrict__ Bt,
                     const float* __restrict__ bias,
                     const float* __restrict__ res, const float* __restrict__ pos,
                     float* __restrict__ C, int K)
{
    __shared__ uint32_t As[128 * PADK];
    __shared__ uint32_t Bs[128 * PADK];

    const int tid = threadIdx.x;
    const int lane = tid & 31;
    const int wid = tid >> 5;
    const int g = lane >> 2, t = lane & 3;     // mma groupID / tid-in-group
    const int wm = wid >> 2, wn = wid & 3;     // warp tile coords
    const int bm = blockIdx.y * 128, bn = blockIdx.x * 128;

    // loader mapping: each thread owns rows (lm, lm+64), k-chunk lk..lk+3
    const int lm = tid >> 2;          // 0..63
    const int lk = (tid & 3) * 4;     // 0,4,8,12

    const float* pA0 = A  + (size_t)(bm + lm) * K + lk;
    const float* pA1 = pA0 + (size_t)64 * K;
    const float* pB0 = Bt + (size_t)(bn + lm) * K + lk;
    const float* pB1 = pB0 + (size_t)64 * K;

    float acc[4][4][4];
    #pragma unroll
    for (int i = 0; i < 4; i++)
        #pragma unroll
        for (int j = 0; j < 4; j++)
            #pragma unroll
            for (int r = 0; r < 4; r++) acc[i][j][r] = 0.f;

    float4 fa0 = *(const float4*)pA0;
    float4 fa1 = *(const float4*)pA1;
    float4 fb0 = *(const float4*)pB0;
    float4 fb1 = *(const float4*)pB1;

    for (int k0 = 0; k0 < K; k0 += 16) {
        // fill smem (tf32 convert)
        {
            uint32_t* s = &As[lm * PADK + lk];
            s[0] = f2tf32(fa0.x); s[1] = f2tf32(fa0.y); s[2] = f2tf32(fa0.z); s[3] = f2tf32(fa0.w);
            s = &As[(lm + 64) * PADK + lk];
            s[0] = f2tf32(fa1.x); s[1] = f2tf32(fa1.y); s[2] = f2tf32(fa1.z); s[3] = f2tf32(fa1.w);
            s = &Bs[lm * PADK + lk];
            s[0] = f2tf32(fb0.x); s[1] = f2tf32(fb0.y); s[2] = f2tf32(fb0.z); s[3] = f2tf32(fb0.w);
            s = &Bs[(lm + 64) * PADK + lk];
            s[0] = f2tf32(fb1.x); s[1] = f2tf32(fb1.y); s[2] = f2tf32(fb1.z); s[3] = f2tf32(fb1.w);
        }
        __syncthreads();

        if (k0 + 16 < K) {
            fa0 = *(const float4*)(pA0 + k0 + 16);
            fa1 = *(const float4*)(pA1 + k0 + 16);
            fb0 = *(const float4*)(pB0 + k0 + 16);
            fb1 = *(const float4*)(pB1 + k0 + 16);
        }

        #pragma unroll
        for (int ks = 0; ks < 2; ks++) {
            const int kb = ks * 8;
            uint32_t a[4][4], b[4][2];
            #pragma unroll
            for (int i = 0; i < 4; i++) {
                int r = (wm * 64 + i * 16 + g) * PADK + kb + t;
                a[i][0] = As[r];
                a[i][1] = As[r + 8 * PADK];
                a[i][2] = As[r + 4];
                a[i][3] = As[r + 8 * PADK + 4];
            }
            #pragma unroll
            for (int j = 0; j < 4; j++) {
                int c = (wn * 32 + j * 8 + g) * PADK + kb + t;
                b[j][0] = Bs[c];
                b[j][1] = Bs[c + 4];
            }
            #pragma unroll
            for (int i = 0; i < 4; i++)
                #pragma unroll
                for (int j = 0; j < 4; j++)
                    mma_tf32(acc[i][j], a[i], b[j]);
        }
        __syncthreads();
    }

    // epilogue: c0/c1 at (row g, col 2t/2t+1), c2/c3 at (row g+8, ...)
    #pragma unroll
    for (int i = 0; i < 4; i++) {
        int r0 = bm + wm * 64 + i * 16 + g;
        #pragma unroll
        for (int j = 0; j < 4; j++) {
            int cg = bn + wn * 32 + j * 8 + t * 2;
            float2 b2 = *(const float2*)&bias[cg];
            float o00 = acc[i][j][0] + b2.x, o01 = acc[i][j][1] + b2.y;
            float o10 = acc[i][j][2] + b2.x, o11 = acc[i][j][3] + b2.y;
            size_t row0 = (size_t)r0 * ND + cg;
            size_t row1 = (size_t)(r0 + 8) * ND + cg;
            if (res) {
                float2 x0 = *(const float2*)&res[row0];
                float2 x1 = *(const float2*)&res[row1];
                o00 += x0.x; o01 += x0.y; o10 += x1.x; o11 += x1.y;
            }
            if (pos) {
                float2 p0 = *(const float2*)&pos[(size_t)(r0 & 63) * ND + cg];
                float2 p1 = *(const float2*)&pos[(size_t)((r0 + 8) & 63) * ND + cg];
                o00 += p0.x; o01 += p0.y; o10 += p1.x; o11 += p1.y;
            }
            *(float2*)&C[row0] = make_float2(o00, o01);
            *(float2*)&C[row1] = make_float2(o10, o11);
        }
    }
}

// ---------------- attention: one block per (b,h) -----------------------------
__global__ __launch_bounds__(256)
void attn_kernel(const float* __restrict__ rel_bias)
{
    extern __shared__ float sm[];
    float* qst = sm;
    float* kst = sm + 64 * 68;
    float* vs  = sm + 2 * 64 * 68;
    float* ps  = vs + 64 * 64;

    const int h = blockIdx.x, b = blockIdx.y;
    const int tid = threadIdx.x;
    const size_t base = (size_t)b * SEQ * ND + h * 64;

    for (int i = tid; i < 64 * 64; i += 256) {
        int s = i >> 6, d = i & 63;
        size_t gidx = base + (size_t)s * ND + d;
        qst[d * 68 + s] = g_q[gidx];
        kst[d * 68 + s] = g_k[gidx];
        vs [s * 64 + d] = g_v[gidx];
    }
    __syncthreads();

    const int tj = tid & 15, ti = tid >> 4;
    const int i0 = ti * 4, j0 = tj * 4;

    float acc[4][4];
    #pragma unroll
    for (int a = 0; a < 4; a++)
        #pragma unroll
        for (int c = 0; c < 4; c++) acc[a][c] = 0.f;

    #pragma unroll 4
    for (int d = 0; d < 64; d++) {
        float4 qv = *(const float4*)&qst[d * 68 + i0];
        float4 kv = *(const float4*)&kst[d * 68 + j0];
        float qa[4] = {qv.x, qv.y, qv.z, qv.w};
        float kb[4] = {kv.x, kv.y, kv.z, kv.w};
        #pragma unroll
        for (int a = 0; a < 4; a++)
            #pragma unroll
            for (int c = 0; c < 4; c++)
                acc[a][c] = fmaf(qa[a], kb[c], acc[a][c]);
    }

    const float* rb = rel_bias + (size_t)h * 64 * 64;
    #pragma unroll
    for (int a = 0; a < 4; a++) {
        float4 b4 = *(const float4*)&rb[(i0 + a) * 64 + j0];
        acc[a][0] = acc[a][0] * 0.125f + b4.x;
        acc[a][1] = acc[a][1] * 0.125f + b4.y;
        acc[a][2] = acc[a][2] * 0.125f + b4.z;
        acc[a][3] = acc[a][3] * 0.125f + b4.w;
    }

    #pragma unroll
    for (int a = 0; a < 4; a++) {
        float mx = fmaxf(fmaxf(acc[a][0], acc[a][1]), fmaxf(acc[a][2], acc[a][3]));
        #pragma unroll
        for (int off = 1; off < 16; off <<= 1)
            mx = fmaxf(mx, __shfl_xor_sync(0xffffffffu, mx, off));
        float s = 0.f;
        #pragma unroll
        for (int c = 0; c < 4; c++) { acc[a][c] = __expf(acc[a][c] - mx); s += acc[a][c]; }
        #pragma unroll
        for (int off = 1; off < 16; off <<= 1)
            s += __shfl_xor_sync(0xffffffffu, s, off);
        float inv = 1.f / s;
        #pragma unroll
        for (int c = 0; c < 4; c++) acc[a][c] *= inv;
        *(float4*)&ps[(i0 + a) * 64 + j0] =
            make_float4(acc[a][0], acc[a][1], acc[a][2], acc[a][3]);
    }
    __syncthreads();

    float oc[4][4];
    #pragma unroll
    for (int a = 0; a < 4; a++)
        #pragma unroll
        for (int c = 0; c < 4; c++) oc[a][c] = 0.f;

    #pragma unroll 4
    for (int j = 0; j < 64; j++) {
        float4 vv = *(const float4*)&vs[j * 64 + j0];
        float vb[4] = {vv.x, vv.y, vv.z, vv.w};
        float pa[4];
        #pragma unroll
        for (int a = 0; a < 4; a++) pa[a] = ps[(i0 + a) * 64 + j];
        #pragma unroll
        for (int a = 0; a < 4; a++)
            #pragma unroll
            for (int c = 0; c < 4; c++)
                oc[a][c] = fmaf(pa[a], vb[c], oc[a][c]);
    }

    #pragma unroll
    for (int a = 0; a < 4; a++)
        *(float4*)&g_o[base + (size_t)(i0 + a) * ND + j0] =
            make_float4(oc[a][0], oc[a][1], oc[a][2], oc[a][3]);
}

// ---------------- LayerNorm ---------------------------------------------------
__device__ __forceinline__ float block_sum(float v, float* red) {
    #pragma unroll
    for (int o = 16; o > 0; o >>= 1) v += __shfl_xor_sync(0xffffffffu, v, o);
    int w = threadIdx.x >> 5;
    if ((threadIdx.x & 31) == 0) red[w] = v;
    __syncthreads();
    if (threadIdx.x < 8) {
        v = red[threadIdx.x];
        #pragma unroll
        for (int o = 4; o > 0; o >>= 1) v += __shfl_xor_sync(0xffu, v, o);
        if (threadIdx.x == 0) red[0] = v;
    }
    __syncthreads();
    float r = red[0];
    __syncthreads();
    return r;
}

__global__ __launch_bounds__(256)
void ln_kernel(const float* __restrict__ gamma, const float* __restrict__ beta,
               float* __restrict__ out)
{
    __shared__ float red[32];
    const size_t row = (size_t)blockIdx.x * ND;
    const int t4 = threadIdx.x * 4;
    float4 v = *(const float4*)&g_x[row + t4];

    float s = v.x + v.y + v.z + v.w;
    float mu = block_sum(s, red) * (1.f / ND);

    float dx = v.x - mu, dy = v.y - mu, dz = v.z - mu, dw = v.w - mu;
    float sq = dx * dx + dy * dy + dz * dz + dw * dw;
    float var = block_sum(sq, red) * (1.f / ND);
    float inv = rsqrtf(var + 1e-5f);

    float4 g4 = *(const float4*)&gamma[t4];
    float4 b4 = *(const float4*)&beta[t4];
    float4 o4;
    o4.x = dx * inv * g4.x + b4.x;
    o4.y = dy * inv * g4.y + b4.y;
    o4.z = dz * inv * g4.z + b4.z;
    o4.w = dw * inv * g4.w + b4.w;
    *(float4*)&out[row + t4] = o4;
}

// ---------------- launch -------------------------------------------------------
extern "C" void kernel_launch(void* const* d_in, const int* in_sizes, int n_in,
                              void* d_out, int out_size)
{
    const float* board = (const float*)d_in[0];
    const float* embW  = (const float*)d_in[1];
    const float* embB  = (const float*)d_in[2];
    const float* pos   = (const float*)d_in[3];
    const float* Wq    = (const float*)d_in[4];
    const float* bq    = (const float*)d_in[5];
    const float* Wk    = (const float*)d_in[6];
    const float* bk    = (const float*)d_in[7];
    const float* Wv    = (const float*)d_in[8];
    const float* bv    = (const float*)d_in[9];
    const float* Wo    = (const float*)d_in[10];
    const float* bo    = (const float*)d_in[11];
    const float* relb  = (const float*)d_in[12];
    const float* lng   = (const float*)d_in[13];
    const float* lnb   = (const float*)d_in[14];
    float* out = (float*)d_out;

    float *xin, *wt, *x, *q, *k, *v, *o;
    cudaGetSymbolAddress((void**)&xin, g_xin);
    cudaGetSymbolAddress((void**)&wt,  g_Wt);
    cudaGetSymbolAddress((void**)&x,   g_x);
    cudaGetSymbolAddress((void**)&q,   g_q);
    cudaGetSymbolAddress((void**)&k,   g_k);
    cudaGetSymbolAddress((void**)&v,   g_v);
    cudaGetSymbolAddress((void**)&o,   g_o);

    board_transpose_kernel<<<NB, 256>>>(board);

    dim3 tb(32, 8);
    dim3 gemm_grid(ND / 128, MR / 128);

    // embed: x = xin @ embW + emb_b + pos   (K = 128 padded)
    transpose_kernel<<<dim3(ND / 32, KPAD / 32), tb>>>(embW, wt, NC, ND, KPAD);
    gemm_mma_kernel<<<gemm_grid, 256>>>(xin, wt, embB, nullptr, pos, x, KPAD);

    // q, k, v  (K = 1024)
    transpose_kernel<<<dim3(ND / 32, ND / 32), tb>>>(Wq, wt, ND, ND, ND);
    gemm_mma_kernel<<<gemm_grid, 256>>>(x, wt, bq, nullptr, nullptr, q, ND);
    transpose_kernel<<<dim3(ND / 32, ND / 32), tb>>>(Wk, wt, ND, ND, ND);
    gemm_mma_kernel<<<gemm_grid, 256>>>(x, wt, bk, nullptr, nullptr, k, ND);
    transpose_kernel<<<dim3(ND / 32, ND / 32), tb>>>(Wv, wt, ND, ND, ND);
    gemm_mma_kernel<<<gemm_grid, 256>>>(x, wt, bv, nullptr, nullptr, v, ND);

    // attention
    const int attn_smem = (2 * 64 * 68 + 2 * 64 * 64) * (int)sizeof(float);
    cudaFuncSetAttribute(attn_kernel, cudaFuncAttributeMaxDynamicSharedMemorySize, attn_smem);
    attn_kernel<<<dim3(NH, NB), 256, attn_smem>>>(relb);

    // y = x + o @ Wo + bo   (into g_x)
    transpose_kernel<<<dim3(ND / 32, ND / 32), tb>>>(Wo, wt, ND, ND, ND);
    gemm_mma_kernel<<<gemm_grid, 256>>>(o, wt, bo, x, nullptr, x, ND);

    ln_kernel<<<MR, 256>>>(lng, lnb, out);
}